// round 16
// baseline (speedup 1.0000x reference)
#include <cuda_runtime.h>
#include <cuda_bf16.h>

// Snack: out[p] = tanh((f[i]-f[j])^T M (f[i]-f[j])), P = 8,388,608, 20 AAs.
// Converged kernel (R12 record config + iteration-0 full prefetch):
//   - symmetric table build: 190 strictly-upper pairs, diag = 0, mirrored
//   - factorized G = (F M) F^T; dist = G[ii]-G[ij]-G[ji]+G[jj]
//   - 512-thread blocks, 3 CTAs/SM (minimal redundant build, 48 warps/SM)
//   - batched ILP-4 gather (8 LDG.128 in flight) — best measured shape
//   - iteration-0's 8 loads issued BEFORE the build: overlaps the ~0.4us
//     build with the first cold DRAM round trip.

#define NUM_AA   20
#define FEAT_DIM 16
#define FPAD     17
#define TBL      (NUM_AA * NUM_AA)
#define NPAIRS   190                   // 20*19/2 strictly upper
#define THREADS  512
#define NF       (NUM_AA * FEAT_DIM)   // 320

__global__ __launch_bounds__(THREADS, 3) void snack_fused_kernel(
    const float*  __restrict__ features,   // [20, 16]
    const float*  __restrict__ M,          // [16, 16]
    const int4*   __restrict__ idx_i4,     // [P/4]
    const int4*   __restrict__ idx_j4,     // [P/4]
    float4*       __restrict__ out4,       // [P/4]
    int n4)
{
    __shared__ float s_F[NUM_AA * FPAD];
    __shared__ float s_M[FEAT_DIM * FEAT_DIM];
    __shared__ float s_FM[NUM_AA * FPAD];
    __shared__ float s_tbl[TBL];

    const int t = threadIdx.x;
    const int stride = gridDim.x * THREADS;
    const int p0 = blockIdx.x * THREADS + t;

    // ── Prefetch the ENTIRE first ILP-4 batch before the table build.
    int4 a0, a1, a2, a3, b0, b1, b2, b3;
    const bool full0 = (p0 + 3 * stride) < n4;
    if (full0) {
        a0 = idx_i4[p0];
        a1 = idx_i4[p0 + stride];
        a2 = idx_i4[p0 + 2 * stride];
        a3 = idx_i4[p0 + 3 * stride];
        b0 = idx_j4[p0];
        b1 = idx_j4[p0 + stride];
        b2 = idx_j4[p0 + 2 * stride];
        b3 = idx_j4[p0 + 3 * stride];
    }

    // ── Table build (overlaps the prefetch's DRAM latency).
    for (int k = t; k < NF; k += THREADS) {
        const int r = k >> 4, c = k & 15;
        s_F[r * FPAD + c] = features[k];
    }
    for (int k = t; k < FEAT_DIM * FEAT_DIM; k += THREADS) s_M[k] = M[k];
    if (t < NUM_AA) s_tbl[t * NUM_AA + t] = 0.0f;   // tanh(0) == 0 exactly
    __syncthreads();

    for (int k = t; k < NF; k += THREADS) {
        const int r = k >> 4, c = k & 15;
        float acc = 0.0f;
#pragma unroll
        for (int y = 0; y < FEAT_DIM; y++)
            acc = fmaf(s_F[r * FPAD + y], s_M[y * FEAT_DIM + c], acc);
        s_FM[r * FPAD + c] = acc;
    }
    __syncthreads();

    if (t < NPAIRS) {
        int i = 0, rem = t;
        while (rem >= NUM_AA - 1 - i) { rem -= NUM_AA - 1 - i; i++; }
        const int j = i + 1 + rem;

        float gii = 0.0f, gij = 0.0f, gji = 0.0f, gjj = 0.0f;
#pragma unroll
        for (int y = 0; y < FEAT_DIM; y++) {
            const float fiy  = s_F[i * FPAD + y];
            const float fjy  = s_F[j * FPAD + y];
            const float fmiy = s_FM[i * FPAD + y];
            const float fmjy = s_FM[j * FPAD + y];
            gii = fmaf(fmiy, fiy, gii);
            gij = fmaf(fmiy, fjy, gij);
            gji = fmaf(fmjy, fiy, gji);
            gjj = fmaf(fmjy, fjy, gjj);
        }
        const float v = tanhf(gii - gij - gji + gjj);
        s_tbl[i * NUM_AA + j] = v;
        s_tbl[j * NUM_AA + i] = v;
    }
    __syncthreads();

    // ── Consume the prefetched batch, then steady ILP-4 gather.
    int p = p0;
    if (full0) {
        float4 o;
        o.x = s_tbl[a0.x * NUM_AA + b0.x];
        o.y = s_tbl[a0.y * NUM_AA + b0.y];
        o.z = s_tbl[a0.z * NUM_AA + b0.z];
        o.w = s_tbl[a0.w * NUM_AA + b0.w];
        out4[p] = o;
        o.x = s_tbl[a1.x * NUM_AA + b1.x];
        o.y = s_tbl[a1.y * NUM_AA + b1.y];
        o.z = s_tbl[a1.z * NUM_AA + b1.z];
        o.w = s_tbl[a1.w * NUM_AA + b1.w];
        out4[p + stride] = o;
        o.x = s_tbl[a2.x * NUM_AA + b2.x];
        o.y = s_tbl[a2.y * NUM_AA + b2.y];
        o.z = s_tbl[a2.z * NUM_AA + b2.z];
        o.w = s_tbl[a2.w * NUM_AA + b2.w];
        out4[p + 2 * stride] = o;
        o.x = s_tbl[a3.x * NUM_AA + b3.x];
        o.y = s_tbl[a3.y * NUM_AA + b3.y];
        o.z = s_tbl[a3.z * NUM_AA + b3.z];
        o.w = s_tbl[a3.w * NUM_AA + b3.w];
        out4[p + 3 * stride] = o;
        p += 4 * stride;
    }

    for (; p + 3 * stride < n4; p += 4 * stride) {
        int4 c0 = idx_i4[p];
        int4 c1 = idx_i4[p + stride];
        int4 c2 = idx_i4[p + 2 * stride];
        int4 c3 = idx_i4[p + 3 * stride];
        int4 d0 = idx_j4[p];
        int4 d1 = idx_j4[p + stride];
        int4 d2 = idx_j4[p + 2 * stride];
        int4 d3 = idx_j4[p + 3 * stride];
        float4 o;
        o.x = s_tbl[c0.x * NUM_AA + d0.x];
        o.y = s_tbl[c0.y * NUM_AA + d0.y];
        o.z = s_tbl[c0.z * NUM_AA + d0.z];
        o.w = s_tbl[c0.w * NUM_AA + d0.w];
        out4[p] = o;
        o.x = s_tbl[c1.x * NUM_AA + d1.x];
        o.y = s_tbl[c1.y * NUM_AA + d1.y];
        o.z = s_tbl[c1.z * NUM_AA + d1.z];
        o.w = s_tbl[c1.w * NUM_AA + d1.w];
        out4[p + stride] = o;
        o.x = s_tbl[c2.x * NUM_AA + d2.x];
        o.y = s_tbl[c2.y * NUM_AA + d2.y];
        o.z = s_tbl[c2.z * NUM_AA + d2.z];
        o.w = s_tbl[c2.w * NUM_AA + d2.w];
        out4[p + 2 * stride] = o;
        o.x = s_tbl[c3.x * NUM_AA + d3.x];
        o.y = s_tbl[c3.y * NUM_AA + d3.y];
        o.z = s_tbl[c3.z * NUM_AA + d3.z];
        o.w = s_tbl[c3.w * NUM_AA + d3.w];
        out4[p + 3 * stride] = o;
    }
    for (; p < n4; p += stride) {
        int4 a = idx_i4[p];
        int4 b = idx_j4[p];
        float4 o;
        o.x = s_tbl[a.x * NUM_AA + b.x];
        o.y = s_tbl[a.y * NUM_AA + b.y];
        o.z = s_tbl[a.z * NUM_AA + b.z];
        o.w = s_tbl[a.w * NUM_AA + b.w];
        out4[p] = o;
    }
}

extern "C" void kernel_launch(void* const* d_in, const int* in_sizes, int n_in,
                              void* d_out, int out_size)
{
    const float* features = (const float*)d_in[0];   // [20,16]
    const float* M        = (const float*)d_in[1];   // [16,16]
    const int*   idx_i    = (const int*)d_in[2];     // [P]
    const int*   idx_j    = (const int*)d_in[3];     // [P]
    float*       out      = (float*)d_out;           // [P]

    const int P  = out_size;   // 8,388,608
    const int n4 = P / 4;      // 2,097,152

    static int blocks = 0;
    if (blocks == 0) {
        int per_sm = 0;
        cudaOccupancyMaxActiveBlocksPerMultiprocessor(
            &per_sm, snack_fused_kernel, THREADS, 0);
        if (per_sm < 1) per_sm = 1;
        int sms = 0;
        cudaDeviceGetAttribute(&sms, cudaDevAttrMultiProcessorCount, 0);
        if (sms <= 0) sms = 148;
        blocks = per_sm * sms;
        int max_blocks = (n4 + THREADS - 1) / THREADS;
        if (blocks > max_blocks) blocks = max_blocks;
    }

    snack_fused_kernel<<<blocks, THREADS>>>(
        features, M,
        (const int4*)idx_i, (const int4*)idx_j,
        (float4*)out, n4);
}

// round 17
// speedup vs baseline: 1.2930x; 1.2930x over previous
#include <cuda_runtime.h>
#include <cuda_bf16.h>

// Snack: out[p] = tanh((f[i]-f[j])^T M (f[i]-f[j])), P = 8,388,608, 20 AAs.
// FINAL kernel (R12 configuration — measured 15.07/15.10us across two holds):
//   - SYMMETRY: dist(i,j)=dist(j,i) for any M; dist(i,i)=0 exactly.
//     -> only 190 strictly-upper pairs computed, mirrored; diag = 0.
//   - 512-thread blocks, 3 CTAs/SM -> minimal redundant per-CTA build
//     at 48 warps/SM for the gather.
//   - factorized G = (F M) F^T; dist = G[ii]-G[ij]-G[ji]+G[jj]
//   - batched ILP-4 gather (8 LDG.128 in flight) — best measured shape.
// At the floor: ~70MB effective DRAM traffic (partial L2 retention across
// graph replays) at the ~6.3TB/s LTS ceiling + build/ramp => ~15us.
// Falsified alternatives: higher occupancy (R9), LDS replication (R8),
// SW pipelining (R7), L2 policy hints (R10/R14), prefetch-over-build
// (R11 neutral, R16 spills).

#define NUM_AA   20
#define FEAT_DIM 16
#define FPAD     17
#define TBL      (NUM_AA * NUM_AA)
#define NPAIRS   190                   // 20*19/2 strictly upper
#define THREADS  512
#define NF       (NUM_AA * FEAT_DIM)   // 320

__global__ __launch_bounds__(THREADS, 3) void snack_fused_kernel(
    const float*  __restrict__ features,   // [20, 16]
    const float*  __restrict__ M,          // [16, 16]
    const int4*   __restrict__ idx_i4,     // [P/4]
    const int4*   __restrict__ idx_j4,     // [P/4]
    float4*       __restrict__ out4,       // [P/4]
    int n4)
{
    __shared__ float s_F[NUM_AA * FPAD];
    __shared__ float s_M[FEAT_DIM * FEAT_DIM];
    __shared__ float s_FM[NUM_AA * FPAD];
    __shared__ float s_tbl[TBL];

    const int t = threadIdx.x;

    // Stage F (padded) and M.
    for (int k = t; k < NF; k += THREADS) {
        const int r = k >> 4, c = k & 15;
        s_F[r * FPAD + c] = features[k];
    }
    for (int k = t; k < FEAT_DIM * FEAT_DIM; k += THREADS) s_M[k] = M[k];
    if (t < NUM_AA) s_tbl[t * NUM_AA + t] = 0.0f;   // tanh(0) == 0 exactly
    __syncthreads();

    // FM = F @ M (320 elements).
    for (int k = t; k < NF; k += THREADS) {
        const int r = k >> 4, c = k & 15;
        float acc = 0.0f;
#pragma unroll
        for (int y = 0; y < FEAT_DIM; y++)
            acc = fmaf(s_F[r * FPAD + y], s_M[y * FEAT_DIM + c], acc);
        s_FM[r * FPAD + c] = acc;
    }
    __syncthreads();

    // 190 strictly-upper pairs; mirror into (i,j) and (j,i).
    if (t < NPAIRS) {
        int i = 0, rem = t;
        while (rem >= NUM_AA - 1 - i) { rem -= NUM_AA - 1 - i; i++; }
        const int j = i + 1 + rem;

        float gii = 0.0f, gij = 0.0f, gji = 0.0f, gjj = 0.0f;
#pragma unroll
        for (int y = 0; y < FEAT_DIM; y++) {
            const float fiy  = s_F[i * FPAD + y];
            const float fjy  = s_F[j * FPAD + y];
            const float fmiy = s_FM[i * FPAD + y];
            const float fmjy = s_FM[j * FPAD + y];
            gii = fmaf(fmiy, fiy, gii);
            gij = fmaf(fmiy, fjy, gij);
            gji = fmaf(fmjy, fiy, gji);
            gjj = fmaf(fmjy, fjy, gjj);
        }
        const float v = tanhf(gii - gij - gji + gjj);
        s_tbl[i * NUM_AA + j] = v;
        s_tbl[j * NUM_AA + i] = v;
    }
    __syncthreads();

    // Batched ILP-4 gather: 8 independent LDG.128 in flight per thread.
    const int stride = gridDim.x * THREADS;
    int p = blockIdx.x * THREADS + t;

    for (; p + 3 * stride < n4; p += 4 * stride) {
        int4 a0 = idx_i4[p];
        int4 a1 = idx_i4[p + stride];
        int4 a2 = idx_i4[p + 2 * stride];
        int4 a3 = idx_i4[p + 3 * stride];
        int4 b0 = idx_j4[p];
        int4 b1 = idx_j4[p + stride];
        int4 b2 = idx_j4[p + 2 * stride];
        int4 b3 = idx_j4[p + 3 * stride];
        float4 o;
        o.x = s_tbl[a0.x * NUM_AA + b0.x];
        o.y = s_tbl[a0.y * NUM_AA + b0.y];
        o.z = s_tbl[a0.z * NUM_AA + b0.z];
        o.w = s_tbl[a0.w * NUM_AA + b0.w];
        out4[p] = o;
        o.x = s_tbl[a1.x * NUM_AA + b1.x];
        o.y = s_tbl[a1.y * NUM_AA + b1.y];
        o.z = s_tbl[a1.z * NUM_AA + b1.z];
        o.w = s_tbl[a1.w * NUM_AA + b1.w];
        out4[p + stride] = o;
        o.x = s_tbl[a2.x * NUM_AA + b2.x];
        o.y = s_tbl[a2.y * NUM_AA + b2.y];
        o.z = s_tbl[a2.z * NUM_AA + b2.z];
        o.w = s_tbl[a2.w * NUM_AA + b2.w];
        out4[p + 2 * stride] = o;
        o.x = s_tbl[a3.x * NUM_AA + b3.x];
        o.y = s_tbl[a3.y * NUM_AA + b3.y];
        o.z = s_tbl[a3.z * NUM_AA + b3.z];
        o.w = s_tbl[a3.w * NUM_AA + b3.w];
        out4[p + 3 * stride] = o;
    }
    for (; p < n4; p += stride) {
        int4 a = idx_i4[p];
        int4 b = idx_j4[p];
        float4 o;
        o.x = s_tbl[a.x * NUM_AA + b.x];
        o.y = s_tbl[a.y * NUM_AA + b.y];
        o.z = s_tbl[a.z * NUM_AA + b.z];
        o.w = s_tbl[a.w * NUM_AA + b.w];
        out4[p] = o;
    }
}

extern "C" void kernel_launch(void* const* d_in, const int* in_sizes, int n_in,
                              void* d_out, int out_size)
{
    const float* features = (const float*)d_in[0];   // [20,16]
    const float* M        = (const float*)d_in[1];   // [16,16]
    const int*   idx_i    = (const int*)d_in[2];     // [P]
    const int*   idx_j    = (const int*)d_in[3];     // [P]
    float*       out      = (float*)d_out;           // [P]

    const int P  = out_size;   // 8,388,608
    const int n4 = P / 4;      // 2,097,152

    static int blocks = 0;
    if (blocks == 0) {
        int per_sm = 0;
        cudaOccupancyMaxActiveBlocksPerMultiprocessor(
            &per_sm, snack_fused_kernel, THREADS, 0);
        if (per_sm < 1) per_sm = 1;
        int sms = 0;
        cudaDeviceGetAttribute(&sms, cudaDevAttrMultiProcessorCount, 0);
        if (sms <= 0) sms = 148;
        blocks = per_sm * sms;
        int max_blocks = (n4 + THREADS - 1) / THREADS;
        if (blocks > max_blocks) blocks = max_blocks;
    }

    snack_fused_kernel<<<blocks, THREADS>>>(
        features, M,
        (const int4*)idx_i, (const int4*)idx_j,
        (float4*)out, n4);
}